// round 11
// baseline (speedup 1.0000x reference)
#include <cuda_runtime.h>
#include <cuda_pipeline_primitives.h>
#include <cstdint>

// cost = 0.5 * sum_n x_n^T C_n x_n
// N_BLOCKS = 8192, BLOCK = 64
// d_in[0] = x [524288] fp32, d_in[1] = C_blocks [8192*64*64] fp32, d_out = [1] fp32

#define N_BLOCKS 8192
#define BLK 64
#define GRID 888                   // 148 SMs * 6 resident CTAs
#define MAXB 10                    // ceil(8192/888)
#define CHUNK_F4 128               // per-warp chunk: 8 rows * 64 cols = 512 floats = 2KB

__device__ double g_acc;            // zero-initialized at module load
__device__ unsigned int g_count;

__global__ __launch_bounds__(256, 6) void quadform_kernel(
    const float* __restrict__ x,
    const float* __restrict__ C,
    float* __restrict__ out)
{
    // Warp-private double buffers: warp w, stage q -> sbuf + (w*2+q)*512 floats.
    __shared__ __align__(16) float sbuf[8 * 2 * 512];   // 32 KB
    __shared__ float xs[MAXB * BLK];                     // 2.5 KB
    __shared__ float warp_sums[8];

    const int t    = threadIdx.x;
    const int lane = t & 31;
    const int wid  = t >> 5;
    const int bid  = blockIdx.x;

    // Interleaved block assignment (R3 style): chunk c -> block bid + c*GRID.
    const int nb = (N_BLOCKS - bid + GRID - 1) / GRID;   // 9 or 10

    const float4* Cg = reinterpret_cast<const float4*>(C);

    // Per-warp chunk source: block n, rows [wid*8, wid*8+8) ->
    // float4 indices n*1024 + wid*128 + (j*32 + lane), j = 0..3.
    const int warp_f4_off = wid * CHUNK_F4;

    // Prologue: issue chunks 0 and 1 (commit #0, #1). Chunk c sits in commit #c.
    #pragma unroll
    for (int c = 0; c < 2; c++) {
        if (c < nb) {
            const size_t gbase = (size_t)(bid + c * GRID) * 1024 + warp_f4_off;
            float4* dst = reinterpret_cast<float4*>(sbuf) + (wid * 2 + c) * CHUNK_F4;
            #pragma unroll
            for (int j = 0; j < 4; j++)
                __pipeline_memcpy_async(&dst[j * 32 + lane], &Cg[gbase + j * 32 + lane], 16);
        }
        __pipeline_commit();
    }

    // Preload x for all of this CTA's blocks; single barrier, then none.
    for (int i = t; i < nb * 16; i += 256) {
        reinterpret_cast<float4*>(xs)[i] =
            reinterpret_cast<const float4*>(x)[(bid + (i >> 4) * GRID) * 16 + (i & 15)];
    }
    __syncthreads();

    float acc0 = 0.f, acc1 = 0.f;
    const int c4    = lane & 15;        // (j*32+lane)&15 == lane&15 : constant col-quad
    const int rhalf = lane >> 4;        // row_local = j*2 + rhalf

    // Main loop: NO CTA barriers. Each warp waits only on its own async groups.
    for (int k = 0; k < nb; k++) {
        // Committed groups so far: k + 2. Chunk k = group #k -> at most the
        // newest 1 group may be pending once chunk k is done.
        __pipeline_wait_prior(1);

        const float*  xb   = xs + k * BLK;
        const float4  xc   = reinterpret_cast<const float4*>(xb)[c4];
        const float4* buf4 = reinterpret_cast<const float4*>(sbuf) + (wid * 2 + (k & 1)) * CHUNK_F4;
        const float*  xrow = xb + wid * 8;

        #pragma unroll
        for (int j = 0; j < 4; j++) {
            const float4 v  = buf4[j * 32 + lane];
            const float  xr = xrow[j * 2 + rhalf];
            const float  d  = v.x * xc.x + v.y * xc.y + v.z * xc.z + v.w * xc.w;
            if (j & 1) acc1 += xr * d; else acc0 += xr * d;
        }

        // Refill the buffer we just drained with chunk k+2 (empty commit in tail
        // keeps the group-FIFO accounting uniform).
        if (k + 2 < nb) {
            const size_t gbase = (size_t)(bid + (k + 2) * GRID) * 1024 + warp_f4_off;
            float4* dst = reinterpret_cast<float4*>(sbuf) + (wid * 2 + (k & 1)) * CHUNK_F4;
            #pragma unroll
            for (int j = 0; j < 4; j++)
                __pipeline_memcpy_async(&dst[j * 32 + lane], &Cg[gbase + j * 32 + lane], 16);
        }
        __pipeline_commit();
    }

    float acc = acc0 + acc1;

    // Intra-CTA reduction
    #pragma unroll
    for (int off = 16; off > 0; off >>= 1)
        acc += __shfl_down_sync(0xFFFFFFFFu, acc, off);
    if (lane == 0) warp_sums[wid] = acc;
    __syncthreads();

    if (wid == 0) {
        float v = (lane < 8) ? warp_sums[lane] : 0.f;
        #pragma unroll
        for (int off = 4; off > 0; off >>= 1)
            v += __shfl_down_sync(0xFFFFFFFFu, v, off);

        if (lane == 0) {
            atomicAdd(&g_acc, (double)v);
            __threadfence();
            unsigned int done = atomicAdd(&g_count, 1u);
            if (done == GRID - 1) {
                double total = atomicAdd(&g_acc, 0.0);
                out[0] = (float)(0.5 * total);
                g_acc = 0.0;
                g_count = 0u;
                __threadfence();
            }
        }
    }
}

extern "C" void kernel_launch(void* const* d_in, const int* in_sizes, int n_in,
                              void* d_out, int out_size) {
    const float* x = (const float*)d_in[0];
    const float* C = (const float*)d_in[1];
    float* out = (float*)d_out;

    quadform_kernel<<<GRID, 256>>>(x, C, out);
}